// round 13
// baseline (speedup 1.0000x reference)
#include <cuda_runtime.h>
#include <cuda_bf16.h>
#include <cstdint>
#include <cstddef>

#define NQ 128
#define CDIM 640
#define NP 1024

// A: 128 rows x 648 bf16 (row 1296 B; stride%128==16 -> LDSM conflict-free)
#define A_ROW_B 1296
#define A_BYTES (128 * A_ROW_B)               /* 165888 */
#define B_OFF   A_BYTES
#define B_ROW_B 144
#define B_BUF_B (128 * B_ROW_B)               /* 18432 */
#define N_STAGE 3
#define RS_OFF  (B_OFF + N_STAGE * B_BUF_B)   /* 221184 */
#define MAIN_SMEM (RS_OFF + (16 * 32 + 8) * 4)
#define P2_SMEM ((640 * 65 + 256 + 64) * 4)
#define NTHR 512

__device__ __align__(16) __nv_bfloat16 g_q[(size_t)NQ * NP * CDIM];
__device__ __align__(16) __nv_bfloat16 g_s[(size_t)NP * CDIM];
__device__ float g_part[NQ * 8];

__device__ __forceinline__ uint32_t smem_u32(const void* p) {
    uint32_t a;
    asm("{ .reg .u64 t; cvta.to.shared.u64 t, %1; cvt.u32.u64 %0, t; }" : "=r"(a) : "l"(p));
    return a;
}
#define CP_ASYNC16(dst, src) \
    asm volatile("cp.async.cg.shared.global [%0], [%1], 16;" :: "r"(dst), "l"(src) : "memory")
#define CP_COMMIT() asm volatile("cp.async.commit_group;" ::: "memory")
#define CP_WAIT(n)  asm volatile("cp.async.wait_group %0;" :: "n"(n) : "memory")

__device__ __forceinline__ void ldsm_x4(uint32_t* r, uint32_t a) {
    asm volatile("ldmatrix.sync.aligned.m8n8.x4.shared.b16 {%0,%1,%2,%3}, [%4];"
        : "=r"(r[0]), "=r"(r[1]), "=r"(r[2]), "=r"(r[3]) : "r"(a));
}
__device__ __forceinline__ void mma16816(float* c, const uint32_t* a, const uint32_t* b) {
    asm volatile(
        "mma.sync.aligned.m16n8k16.row.col.f32.bf16.bf16.f32 "
        "{%0,%1,%2,%3}, {%4,%5,%6,%7}, {%8,%9}, {%0,%1,%2,%3};"
        : "+f"(c[0]), "+f"(c[1]), "+f"(c[2]), "+f"(c[3])
        : "r"(a[0]), "r"(a[1]), "r"(a[2]), "r"(a[3]), "r"(b[0]), "r"(b[1]));
}

// ---------------- P1: support prototype + L2 norm --------------------------
__global__ void prep_support(const float* __restrict__ sup) {
    __shared__ float red[256];
    __shared__ float inv[64];
    int t = threadIdx.x, r = t >> 6, ml = t & 63;
    int m0 = blockIdx.x * 64;
    float ssq = 0.f;
    for (int c = r; c < CDIM; c += 4) {
        float s = 0.f;
        #pragma unroll
        for (int sh = 0; sh < 5; sh++) s += sup[((size_t)sh * CDIM + c) * NP + m0 + ml];
        float p = s * 0.2f;
        ssq += p * p;
    }
    red[t] = ssq;
    __syncthreads();
    if (t < 64)
        inv[t] = 1.f / fmaxf(sqrtf(red[t] + red[t + 64] + red[t + 128] + red[t + 192]), 1e-12f);
    __syncthreads();
    float iv = inv[ml];
    for (int c = r; c < CDIM; c += 4) {
        float s = 0.f;
        #pragma unroll
        for (int sh = 0; sh < 5; sh++) s += sup[((size_t)sh * CDIM + c) * NP + m0 + ml];
        g_s[(size_t)(m0 + ml) * CDIM + c] = __float2bfloat16(s * 0.2f * iv);
    }
}

// ---------------- P2: query normalize + transpose --------------------------
__global__ void __launch_bounds__(256, 1) prep_query(const float* __restrict__ qf) {
    extern __shared__ unsigned char sm2[];
    float* tile = reinterpret_cast<float*>(sm2);   // [640][65]
    float* red  = tile + 640 * 65;
    float* inv  = red + 256;
    int t = threadIdx.x, r = t >> 6, nl = t & 63;
    int q = blockIdx.y, n0 = blockIdx.x * 64;
    const float* src = qf + (size_t)q * CDIM * NP + n0;
    float ssq = 0.f;
    for (int c = r; c < CDIM; c += 4) {
        float v = src[(size_t)c * NP + nl];
        tile[c * 65 + nl] = v;
        ssq += v * v;
    }
    red[t] = ssq;
    __syncthreads();
    if (t < 64)
        inv[t] = 1.f / fmaxf(sqrtf(red[t] + red[t + 64] + red[t + 128] + red[t + 192]), 1e-12f);
    __syncthreads();
    for (int n = 0; n < 64; n++) {
        float iv = inv[n];
        __nv_bfloat162* row =
            reinterpret_cast<__nv_bfloat162*>(g_q + ((size_t)q * NP + n0 + n) * CDIM);
        for (int p = t; p < 320; p += 256) {
            int c = p << 1;
            __nv_bfloat162 o;
            o.x = __float2bfloat16(tile[c * 65 + n] * iv);
            o.y = __float2bfloat16(tile[(c + 1) * 65 + n] * iv);
            row[p] = o;
        }
    }
}

// ---------------- P3: main HMMA GEMM + rowmax -------------------------------
// 512 threads / 16 warps: 4 warps per SMSP (occupancy experiment).
// Warp tile 32m x 32n; warp grid 4x4 over the 128x128 (M x N-tile) block.
// A resident; B streamed 8 N-tiles x 10 K-chunks, round-10 pipeline skeleton.
__global__ void __launch_bounds__(NTHR, 1) sim_kernel() {
    extern __shared__ unsigned char sm[];
    const uint32_t sbase = smem_u32(sm);
    const int tid = threadIdx.x, wid = tid >> 5, lid = tid & 31;
    const int g = lid >> 2, t = lid & 3;
    const int mat = lid >> 3, mi = lid & 7;
    const int wm = (wid >> 2) * 32, wn = (wid & 3) * 32;
    const int bid = blockIdx.x, q = bid >> 3, mt = bid & 7;

    // A tile: own cp.async group (overlaps B0/B1 fetch)
    const __nv_bfloat16* qa = g_q + ((size_t)q * NP + mt * 128) * CDIM;
    for (int i = tid; i < 10240; i += NTHR) {
        int m = i / 80, v = i % 80;
        CP_ASYNC16(sbase + m * A_ROW_B + v * 16, qa + (size_t)m * CDIM + v * 8);
    }
    CP_COMMIT();

    const int r8 = tid >> 3, c8 = tid & 7;
    auto loadB = [&](int n0, int kc, int buf) {
        uint32_t dstb = sbase + B_OFF + buf * B_BUF_B;
        const __nv_bfloat16* s0 = g_s + (size_t)n0 * CDIM + kc * 64 + c8 * 8;
        #pragma unroll
        for (int it = 0; it < 2; it++) {
            int r = r8 + it * 64;
            CP_ASYNC16(dstb + r * B_ROW_B + c8 * 16, s0 + (size_t)r * CDIM);
        }
        CP_COMMIT();
    };
    loadB(0, 0, 0);
    loadB(0, 1, 1);

    // ldmatrix bases (verified mapping; warp tile 32x32)
    uint32_t abase[2];
    #pragma unroll
    for (int ms = 0; ms < 2; ms++)
        abase[ms] = sbase + (wm + ms * 16 + (mat & 1) * 8 + mi) * A_ROW_B + (mat >> 1) * 16;
    uint32_t bloff[2];
    #pragma unroll
    for (int p = 0; p < 2; p++)
        bloff[p] = (wn + p * 16 + (mat >> 1) * 8 + mi) * B_ROW_B + (mat & 1) * 16;

    float acc[2][4][4];
    float rmax4[4] = {-3.0e38f, -3.0e38f, -3.0e38f, -3.0e38f};
    int cbuf = 0, wbuf = 2;
    int fnt = 0, fkc = 2;
    int j = 0;

    for (int nt = 0; nt < 8; nt++) {
        #pragma unroll
        for (int ms = 0; ms < 2; ms++)
            #pragma unroll
            for (int ns = 0; ns < 4; ns++)
                #pragma unroll
                for (int v = 0; v < 4; v++) acc[ms][ns][v] = 0.f;

        for (int kc = 0; kc < 10; kc++, j++) {
            if (j < 78) {
                loadB(fnt << 7, fkc, wbuf);
                if (++wbuf == N_STAGE) wbuf = 0;
                if (++fkc == 10) { fkc = 0; fnt++; }
                CP_WAIT(2);
            } else if (j == 78) { CP_WAIT(1); }
            else                { CP_WAIT(0); }
            __syncthreads();

            const uint32_t bb = sbase + B_OFF + cbuf * B_BUF_B;
            const uint32_t akb = (uint32_t)kc * 128;
            #pragma unroll
            for (int ks = 0; ks < 4; ks++) {
                uint32_t a0[4], a1[4], br[4];
                ldsm_x4(a0, abase[0] + akb + ks * 32);
                ldsm_x4(a1, abase[1] + akb + ks * 32);
                #pragma unroll
                for (int p = 0; p < 2; p++) {
                    ldsm_x4(br, bb + bloff[p] + ks * 32);
                    mma16816(acc[0][2 * p + 0], a0, &br[0]);
                    mma16816(acc[0][2 * p + 1], a0, &br[2]);
                    mma16816(acc[1][2 * p + 0], a1, &br[0]);
                    mma16816(acc[1][2 * p + 1], a1, &br[2]);
                }
            }
            if (++cbuf == N_STAGE) cbuf = 0;
            __syncthreads();
        }
        // fold this N-tile's rowmax
        #pragma unroll
        for (int ms = 0; ms < 2; ms++)
            #pragma unroll
            for (int ns = 0; ns < 4; ns++) {
                rmax4[ms * 2 + 0] = fmaxf(rmax4[ms * 2 + 0], fmaxf(acc[ms][ns][0], acc[ms][ns][1]));
                rmax4[ms * 2 + 1] = fmaxf(rmax4[ms * 2 + 1], fmaxf(acc[ms][ns][2], acc[ms][ns][3]));
            }
    }

    // reduce: lanes t (same rows) -> 4 n-warps per m-group -> sum 128 rowmaxes
    float* rs = reinterpret_cast<float*>(sm + RS_OFF);   // [16][32] + [8]
    #pragma unroll
    for (int m4 = 0; m4 < 4; m4++) {
        float v = rmax4[m4];
        v = fmaxf(v, __shfl_xor_sync(0xffffffffu, v, 1));
        v = fmaxf(v, __shfl_xor_sync(0xffffffffu, v, 2));
        rmax4[m4] = v;
    }
    if (t == 0) {
        // warp's 32 rows: [ms*16 + e*8 + g]
        rs[wid * 32 + g]      = rmax4[0];
        rs[wid * 32 + 8 + g]  = rmax4[1];
        rs[wid * 32 + 16 + g] = rmax4[2];
        rs[wid * 32 + 24 + g] = rmax4[3];
    }
    __syncthreads();
    if (tid < 128) {
        int r = tid;                       // global row
        int mg = r >> 5, rl = r & 31;      // m-group, local row
        float v = fmaxf(fmaxf(rs[(mg * 4 + 0) * 32 + rl], rs[(mg * 4 + 1) * 32 + rl]),
                        fmaxf(rs[(mg * 4 + 2) * 32 + rl], rs[(mg * 4 + 3) * 32 + rl]));
        #pragma unroll
        for (int o = 16; o; o >>= 1) v += __shfl_xor_sync(0xffffffffu, v, o);
        if ((tid & 31) == 0) rs[512 + (tid >> 5)] = v;
    }
    __syncthreads();
    if (tid == 0) g_part[bid] = rs[512] + rs[513] + rs[514] + rs[515];
}

// ---------------- P4: deterministic reduce ----------------------------------
__global__ void finalize_kernel(float* __restrict__ out) {
    int q = threadIdx.x;
    float s = 0.f;
    #pragma unroll
    for (int mt = 0; mt < 8; mt++) s += g_part[q * 8 + mt];
    out[q] = s * (1.0f / 1024.0f);
}

extern "C" void kernel_launch(void* const* d_in, const int* in_sizes, int n_in,
                              void* d_out, int out_size) {
    const float* qf = (const float*)d_in[0];
    const float* sf = (const float*)d_in[1];
    float* out = (float*)d_out;
    cudaFuncSetAttribute(prep_query, cudaFuncAttributeMaxDynamicSharedMemorySize, P2_SMEM);
    cudaFuncSetAttribute(sim_kernel, cudaFuncAttributeMaxDynamicSharedMemorySize, MAIN_SMEM);
    prep_support<<<16, 256>>>(sf);
    dim3 g2(16, 128);
    prep_query<<<g2, 256, P2_SMEM>>>(qf);
    sim_kernel<<<1024, NTHR, MAIN_SMEM>>>();
    finalize_kernel<<<1, 128>>>(out);
}

// round 15
// speedup vs baseline: 1.5220x; 1.5220x over previous
#include <cuda_runtime.h>
#include <cuda_fp16.h>
#include <cstdint>
#include <cstddef>

#define NQ 128
#define CDIM 640
#define NP 1024

// A: 128 rows x 648 f16 (row 1296 B; stride%128==16 -> LDSM conflict-free)
#define A_ROW_B 1296
#define A_BYTES (128 * A_ROW_B)               /* 165888 */
#define B_OFF   A_BYTES
#define B_ROW_B 144
#define B_BUF_B (128 * B_ROW_B)               /* 18432 */
#define N_STAGE 3
#define NORM_OFF (B_OFF + N_STAGE * B_BUF_B)  /* 221184: inv-norms[128] f32 */
#define RS_OFF   (NORM_OFF + 512)             /* 221696 */
#define MAIN_SMEM (RS_OFF + (8 * 32 + 8) * 4) /* 222752 */
// staging tile (reuses B region before pipeline starts): 64 c x 130 f32
#define STG_PAD 130

__device__ __align__(16) __half g_s[(size_t)NP * CDIM];   // [n][c] normalized proto
__device__ float g_part[NQ * 8];

__device__ __forceinline__ uint32_t smem_u32(const void* p) {
    uint32_t a;
    asm("{ .reg .u64 t; cvta.to.shared.u64 t, %1; cvt.u32.u64 %0, t; }" : "=r"(a) : "l"(p));
    return a;
}
#define CP_ASYNC16(dst, src) \
    asm volatile("cp.async.cg.shared.global [%0], [%1], 16;" :: "r"(dst), "l"(src) : "memory")
#define CP_COMMIT() asm volatile("cp.async.commit_group;" ::: "memory")
#define CP_WAIT(n)  asm volatile("cp.async.wait_group %0;" :: "n"(n) : "memory")

__device__ __forceinline__ void ldsm_x4(uint32_t* r, uint32_t a) {
    asm volatile("ldmatrix.sync.aligned.m8n8.x4.shared.b16 {%0,%1,%2,%3}, [%4];"
        : "=r"(r[0]), "=r"(r[1]), "=r"(r[2]), "=r"(r[3]) : "r"(a));
}
__device__ __forceinline__ void mma16816(float* c, const uint32_t* a, const uint32_t* b) {
    asm volatile(
        "mma.sync.aligned.m16n8k16.row.col.f32.f16.f16.f32 "
        "{%0,%1,%2,%3}, {%4,%5,%6,%7}, {%8,%9}, {%0,%1,%2,%3};"
        : "+f"(c[0]), "+f"(c[1]), "+f"(c[2]), "+f"(c[3])
        : "r"(a[0]), "r"(a[1]), "r"(a[2]), "r"(a[3]), "r"(b[0]), "r"(b[1]));
}

// ---------------- P1: support prototype + L2 norm -> g_s f16 [n][c] --------
__global__ void prep_support(const float* __restrict__ sup) {
    __shared__ float red[256];
    __shared__ float inv[64];
    int t = threadIdx.x, r = t >> 6, ml = t & 63;
    int m0 = blockIdx.x * 64;
    float ssq = 0.f;
    for (int c = r; c < CDIM; c += 4) {
        float s = 0.f;
        #pragma unroll
        for (int sh = 0; sh < 5; sh++) s += sup[((size_t)sh * CDIM + c) * NP + m0 + ml];
        float p = s * 0.2f;
        ssq += p * p;
    }
    red[t] = ssq;
    __syncthreads();
    if (t < 64)
        inv[t] = 1.f / fmaxf(sqrtf(red[t] + red[t + 64] + red[t + 128] + red[t + 192]), 1e-12f);
    __syncthreads();
    float iv = inv[ml];
    for (int c = r; c < CDIM; c += 4) {
        float s = 0.f;
        #pragma unroll
        for (int sh = 0; sh < 5; sh++) s += sup[((size_t)sh * CDIM + c) * NP + m0 + ml];
        g_s[(size_t)(m0 + ml) * CDIM + c] = __float2half_rn(s * 0.2f * iv);
    }
}

// ---------------- P2(main): fused A-prep + HMMA GEMM + rowmax ---------------
// bid = q*8 + mt. A-prep: raw fp32 query (c-major) -> transpose -> f16 smem,
// fp32 row sumsq on the fly (positive scaling commutes with max: apply
// 1/||q_row|| to the rowmax in the epilogue instead of normalizing A).
__global__ void __launch_bounds__(256, 1) sim_kernel(const float* __restrict__ qf) {
    extern __shared__ unsigned char sm[];
    const uint32_t sbase = smem_u32(sm);
    const int tid = threadIdx.x, wid = tid >> 5, lid = tid & 31;
    const int g = lid >> 2, t = lid & 3;
    const int mat = lid >> 3, mi = lid & 7;
    const int wm = (wid >> 1) * 32, wn = (wid & 1) * 64;
    const int bid = blockIdx.x, q = bid >> 3, mt = bid & 7;

    // ======== A-prep staging: 10 chunks of 64 c x 128 n ========
    float* stage = reinterpret_cast<float*>(sm + B_OFF);   // [64][130]
    float* invn  = reinterpret_cast<float*>(sm + NORM_OFF);
    const int c_l = tid >> 3, w = tid & 7;        // pass-1 roles
    const int pn = tid >> 1, pcg = tid & 1;       // pass-2 roles
    const float4* q4 = reinterpret_cast<const float4*>(qf)
                     + ((size_t)q * CDIM) * 256 + mt * 32;
    __half* Ah = reinterpret_cast<__half*>(sm);
    float ss = 0.f;

    for (int i = 0; i < 10; i++) {
        // pass 1: full 64c x 128n chunk (8 float4 per thread, MLP=8)
        {
            const float4* qc = q4 + (size_t)(i * 64 + c_l) * 256;
            float4 rr[8];
            #pragma unroll
            for (int k = 0; k < 4; k++) rr[k] = qc[w + 8 * k];
            #pragma unroll
            for (int k = 0; k < 4; k++) rr[4 + k] = qc[(size_t)32 * 256 + w + 8 * k];
            #pragma unroll
            for (int k = 0; k < 4; k++) {
                float* s0 = stage + c_l * STG_PAD + (w + 8 * k) * 4;
                s0[0] = rr[k].x; s0[1] = rr[k].y; s0[2] = rr[k].z; s0[3] = rr[k].w;
                float* s1 = stage + (c_l + 32) * STG_PAD + (w + 8 * k) * 4;
                s1[0] = rr[4+k].x; s1[1] = rr[4+k].y; s1[2] = rr[4+k].z; s1[3] = rr[4+k].w;
            }
        }
        __syncthreads();
        // pass 2: transpose+convert -> A[n][c] f16, accumulate sumsq (fp32)
        {
            const int c0 = i * 64;
            __half hprev = __float2half_rn(0.f);
            #pragma unroll
            for (int ii = 0; ii < 32; ii++) {
                int cl = ((ii >> 3) << 4) + pcg * 8 + (ii & 7);
                float v = stage[cl * STG_PAD + pn];
                ss += v * v;
                __half h = __float2half_rn(v);
                if (ii & 1) {
                    __half2 h2 = __halves2half2(hprev, h);
                    *reinterpret_cast<__half2*>(
                        reinterpret_cast<char*>(Ah) + pn * A_ROW_B + (c0 + cl - 1) * 2) = h2;
                }
                hprev = h;
            }
        }
        __syncthreads();
    }
    // row inv-norms (deterministic pair reduce over pcg halves)
    {
        float s2 = ss + __shfl_xor_sync(0xffffffffu, ss, 1);
        if (pcg == 0) invn[pn] = 1.f / fmaxf(sqrtf(s2), 1e-12f);
    }
    __syncthreads();

    // ======== round-10 mainloop (f16 operands) ========
    const int r8 = tid >> 3, c8 = tid & 7;
    auto loadB = [&](int n0, int kc, int buf) {
        uint32_t dstb = sbase + B_OFF + buf * B_BUF_B;
        const __half* s0 = g_s + (size_t)n0 * CDIM + kc * 64 + c8 * 8;
        #pragma unroll
        for (int it = 0; it < 4; it++) {
            int r = r8 + it * 32;
            CP_ASYNC16(dstb + r * B_ROW_B + c8 * 16, s0 + (size_t)r * CDIM);
        }
        CP_COMMIT();
    };
    loadB(0, 0, 0);
    loadB(0, 1, 1);

    uint32_t abase[2];
    #pragma unroll
    for (int ms = 0; ms < 2; ms++)
        abase[ms] = sbase + (wm + ms * 16 + (mat & 1) * 8 + mi) * A_ROW_B + (mat >> 1) * 16;
    uint32_t bloff[4];
    #pragma unroll
    for (int p = 0; p < 4; p++)
        bloff[p] = (wn + p * 16 + (mat >> 1) * 8 + mi) * B_ROW_B + (mat & 1) * 16;

    float acc[2][8][4];
    float rmax4[4] = {-3.0e38f, -3.0e38f, -3.0e38f, -3.0e38f};
    int cbuf = 0, wbuf = 2;
    int fnt = 0, fkc = 2;
    int j = 0;

    for (int nt = 0; nt < 8; nt++) {
        #pragma unroll
        for (int ms = 0; ms < 2; ms++)
            #pragma unroll
            for (int ns = 0; ns < 8; ns++)
                #pragma unroll
                for (int v = 0; v < 4; v++) acc[ms][ns][v] = 0.f;

        for (int kc = 0; kc < 10; kc++, j++) {
            if (j < 78) {
                loadB(fnt << 7, fkc, wbuf);
                if (++wbuf == N_STAGE) wbuf = 0;
                if (++fkc == 10) { fkc = 0; fnt++; }
                CP_WAIT(2);
            } else if (j == 78) { CP_WAIT(1); }
            else                { CP_WAIT(0); }
            __syncthreads();

            const uint32_t bb = sbase + B_OFF + cbuf * B_BUF_B;
            const uint32_t akb = (uint32_t)kc * 128;
            #pragma unroll
            for (int ks = 0; ks < 4; ks++) {
                uint32_t a0[4], a1[4], br[4];
                ldsm_x4(a0, abase[0] + akb + ks * 32);
                ldsm_x4(a1, abase[1] + akb + ks * 32);
                #pragma unroll
                for (int p = 0; p < 4; p++) {
                    ldsm_x4(br, bb + bloff[p] + ks * 32);
                    mma16816(acc[0][2 * p + 0], a0, &br[0]);
                    mma16816(acc[0][2 * p + 1], a0, &br[2]);
                    mma16816(acc[1][2 * p + 0], a1, &br[0]);
                    mma16816(acc[1][2 * p + 1], a1, &br[2]);
                }
            }
            if (++cbuf == N_STAGE) cbuf = 0;
            __syncthreads();
        }
        #pragma unroll
        for (int ms = 0; ms < 2; ms++)
            #pragma unroll
            for (int ns = 0; ns < 8; ns++) {
                rmax4[ms * 2 + 0] = fmaxf(rmax4[ms * 2 + 0], fmaxf(acc[ms][ns][0], acc[ms][ns][1]));
                rmax4[ms * 2 + 1] = fmaxf(rmax4[ms * 2 + 1], fmaxf(acc[ms][ns][2], acc[ms][ns][3]));
            }
    }

    // reduce: lanes t -> apply 1/||q_row|| -> warpN pairs -> sum 128 rowmaxes
    float* rs = reinterpret_cast<float*>(sm + RS_OFF);
    #pragma unroll
    for (int m4 = 0; m4 < 4; m4++) {
        float v = rmax4[m4];
        v = fmaxf(v, __shfl_xor_sync(0xffffffffu, v, 1));
        v = fmaxf(v, __shfl_xor_sync(0xffffffffu, v, 2));
        rmax4[m4] = v;
    }
    if (t == 0) {
        rs[wid * 32 + g]      = rmax4[0] * invn[wm + g];
        rs[wid * 32 + 8 + g]  = rmax4[1] * invn[wm + 8 + g];
        rs[wid * 32 + 16 + g] = rmax4[2] * invn[wm + 16 + g];
        rs[wid * 32 + 24 + g] = rmax4[3] * invn[wm + 24 + g];
    }
    __syncthreads();
    if (tid < 128) {
        int wmi = tid >> 5, r = tid & 31;
        float v = fmaxf(rs[(2 * wmi) * 32 + r], rs[(2 * wmi + 1) * 32 + r]);
        #pragma unroll
        for (int o = 16; o; o >>= 1) v += __shfl_xor_sync(0xffffffffu, v, o);
        if ((tid & 31) == 0) rs[256 + (tid >> 5)] = v;
    }
    __syncthreads();
    if (tid == 0) g_part[bid] = rs[256] + rs[257] + rs[258] + rs[259];
}

// ---------------- P4: deterministic reduce ----------------------------------
__global__ void finalize_kernel(float* __restrict__ out) {
    int q = threadIdx.x;
    float s = 0.f;
    #pragma unroll
    for (int mt = 0; mt < 8; mt++) s += g_part[q * 8 + mt];
    out[q] = s * (1.0f / 1024.0f);
}

extern "C" void kernel_launch(void* const* d_in, const int* in_sizes, int n_in,
                              void* d_out, int out_size) {
    const float* qf = (const float*)d_in[0];
    const float* sf = (const float*)d_in[1];
    float* out = (float*)d_out;
    cudaFuncSetAttribute(sim_kernel, cudaFuncAttributeMaxDynamicSharedMemorySize, MAIN_SMEM);
    prep_support<<<16, 256>>>(sf);
    sim_kernel<<<1024, 256, MAIN_SMEM>>>(qf);
    finalize_kernel<<<1, 128>>>(out);
}

// round 16
// speedup vs baseline: 1.7836x; 1.1719x over previous
#include <cuda_runtime.h>
#include <cuda_fp16.h>
#include <cstdint>
#include <cstddef>

#define NQ 128
#define CDIM 640
#define NP 1024

// A: 128 rows x 648 f16 (row 1296 B; stride%128==16 -> LDSM conflict-free)
#define A_ROW_B 1296
#define A_BYTES (128 * A_ROW_B)               /* 165888 */
#define B_OFF   A_BYTES
#define B_ROW_B 144
#define B_BUF_B (128 * B_ROW_B)               /* 18432 */
#define N_STAGE 3
#define NORM_OFF (B_OFF + N_STAGE * B_BUF_B)  /* 221184: inv-norms[128] f32 */
#define RS_OFF   (NORM_OFF + 512)             /* 221696 */
#define MAIN_SMEM (RS_OFF + (8 * 32 + 8) * 4) /* 222752 */
#define STG_PAD 130

__device__ __align__(16) __half g_s[(size_t)NP * CDIM];   // [n][c] normalized proto
__device__ float g_part[NQ * 8];

__device__ __forceinline__ uint32_t smem_u32(const void* p) {
    uint32_t a;
    asm("{ .reg .u64 t; cvta.to.shared.u64 t, %1; cvt.u32.u64 %0, t; }" : "=r"(a) : "l"(p));
    return a;
}
#define CP_ASYNC16(dst, src) \
    asm volatile("cp.async.cg.shared.global [%0], [%1], 16;" :: "r"(dst), "l"(src) : "memory")
#define CP_COMMIT() asm volatile("cp.async.commit_group;" ::: "memory")
#define CP_WAIT(n)  asm volatile("cp.async.wait_group %0;" :: "n"(n) : "memory")

__device__ __forceinline__ void ldsm_x4(uint32_t* r, uint32_t a) {
    asm volatile("ldmatrix.sync.aligned.m8n8.x4.shared.b16 {%0,%1,%2,%3}, [%4];"
        : "=r"(r[0]), "=r"(r[1]), "=r"(r[2]), "=r"(r[3]) : "r"(a));
}
__device__ __forceinline__ void mma16816(float* c, const uint32_t* a, const uint32_t* b) {
    asm volatile(
        "mma.sync.aligned.m16n8k16.row.col.f32.f16.f16.f32 "
        "{%0,%1,%2,%3}, {%4,%5,%6,%7}, {%8,%9}, {%0,%1,%2,%3};"
        : "+f"(c[0]), "+f"(c[1]), "+f"(c[2]), "+f"(c[3])
        : "r"(a[0]), "r"(a[1]), "r"(a[2]), "r"(a[3]), "r"(b[0]), "r"(b[1]));
}

// ---------------- P1: support prototype + L2 norm -> g_s f16 [n][c] --------
// grid 128 x 8 rows: full-chip parallelism, input read once (smem proto cache).
__global__ void __launch_bounds__(256, 1) prep_support(const float* __restrict__ sup) {
    __shared__ float proto[8 * 648];     // [ml][c], padded row
    __shared__ float red[256];
    __shared__ float inv[8];
    const int tid = threadIdx.x;
    const int r = tid >> 3, ml = tid & 7;          // 32 channel lanes x 8 rows
    const int m0 = blockIdx.x * 8;
    const float* base = sup + m0 + ml;
    float ssq = 0.f;
    for (int c = r; c < CDIM; c += 32) {
        float s = 0.f;
        #pragma unroll
        for (int sh = 0; sh < 5; sh++) s += base[((size_t)sh * CDIM + c) * NP];
        float p = s * 0.2f;
        proto[ml * 648 + c] = p;
        ssq += p * p;
    }
    red[tid] = ssq;
    __syncthreads();
    // reduce 32 partials per row (threads with same ml are tid = ml + 8*r)
    if (tid < 8) {
        float s = 0.f;
        #pragma unroll
        for (int rr = 0; rr < 32; rr++) s += red[tid + 8 * rr];
        inv[tid] = 1.f / fmaxf(sqrtf(s), 1e-12f);
    }
    __syncthreads();
    const float iv = inv[ml];
    __half* dst = g_s + (size_t)(m0 + ml) * CDIM;
    for (int c = r; c < CDIM; c += 32)
        dst[c] = __float2half_rn(proto[ml * 648 + c] * iv);
}

// ---------------- P2(main): fused A-prep + HMMA GEMM + rowmax ---------------
// bid = q*8 + mt. A-prep: raw fp32 query (c-major) -> transpose -> f16 smem,
// fp32 row sumsq on the fly (positive scaling commutes with max: apply
// 1/||q_row|| to the rowmax in the epilogue instead of normalizing A).
__global__ void __launch_bounds__(256, 1) sim_kernel(const float* __restrict__ qf) {
    extern __shared__ unsigned char sm[];
    const uint32_t sbase = smem_u32(sm);
    const int tid = threadIdx.x, wid = tid >> 5, lid = tid & 31;
    const int g = lid >> 2, t = lid & 3;
    const int mat = lid >> 3, mi = lid & 7;
    const int wm = (wid >> 1) * 32, wn = (wid & 1) * 64;
    const int bid = blockIdx.x, q = bid >> 3, mt = bid & 7;

    // ======== A-prep staging: 10 chunks of 64 c x 128 n ========
    float* stage = reinterpret_cast<float*>(sm + B_OFF);   // [64][130]
    float* invn  = reinterpret_cast<float*>(sm + NORM_OFF);
    const int c_l = tid >> 3, w = tid & 7;        // pass-1 roles
    const int pn = tid >> 1, pcg = tid & 1;       // pass-2 roles
    const float4* q4 = reinterpret_cast<const float4*>(qf)
                     + ((size_t)q * CDIM) * 256 + mt * 32;
    __half* Ah = reinterpret_cast<__half*>(sm);
    float ss = 0.f;

    for (int i = 0; i < 10; i++) {
        // pass 1: full 64c x 128n chunk (8 float4 per thread, MLP=8)
        {
            const float4* qc = q4 + (size_t)(i * 64 + c_l) * 256;
            float4 rr[8];
            #pragma unroll
            for (int k = 0; k < 4; k++) rr[k] = qc[w + 8 * k];
            #pragma unroll
            for (int k = 0; k < 4; k++) rr[4 + k] = qc[(size_t)32 * 256 + w + 8 * k];
            #pragma unroll
            for (int k = 0; k < 4; k++) {
                float* s0 = stage + c_l * STG_PAD + (w + 8 * k) * 4;
                s0[0] = rr[k].x; s0[1] = rr[k].y; s0[2] = rr[k].z; s0[3] = rr[k].w;
                float* s1 = stage + (c_l + 32) * STG_PAD + (w + 8 * k) * 4;
                s1[0] = rr[4+k].x; s1[1] = rr[4+k].y; s1[2] = rr[4+k].z; s1[3] = rr[4+k].w;
            }
        }
        __syncthreads();
        // pass 2: transpose+convert -> A[n][c] f16, accumulate sumsq (fp32)
        {
            const int c0 = i * 64;
            __half hprev = __float2half_rn(0.f);
            #pragma unroll
            for (int ii = 0; ii < 32; ii++) {
                int cl = ((ii >> 3) << 4) + pcg * 8 + (ii & 7);
                float v = stage[cl * STG_PAD + pn];
                ss += v * v;
                __half h = __float2half_rn(v);
                if (ii & 1) {
                    __half2 h2 = __halves2half2(hprev, h);
                    *reinterpret_cast<__half2*>(
                        reinterpret_cast<char*>(Ah) + pn * A_ROW_B + (c0 + cl - 1) * 2) = h2;
                }
                hprev = h;
            }
        }
        __syncthreads();
    }
    // row inv-norms (deterministic pair reduce over pcg halves)
    {
        float s2 = ss + __shfl_xor_sync(0xffffffffu, ss, 1);
        if (pcg == 0) invn[pn] = 1.f / fmaxf(sqrtf(s2), 1e-12f);
    }
    __syncthreads();

    // ======== mainloop (f16 operands) ========
    const int r8 = tid >> 3, c8 = tid & 7;
    auto loadB = [&](int n0, int kc, int buf) {
        uint32_t dstb = sbase + B_OFF + buf * B_BUF_B;
        const __half* s0 = g_s + (size_t)n0 * CDIM + kc * 64 + c8 * 8;
        #pragma unroll
        for (int it = 0; it < 4; it++) {
            int r = r8 + it * 32;
            CP_ASYNC16(dstb + r * B_ROW_B + c8 * 16, s0 + (size_t)r * CDIM);
        }
        CP_COMMIT();
    };
    loadB(0, 0, 0);
    loadB(0, 1, 1);

    uint32_t abase[2];
    #pragma unroll
    for (int ms = 0; ms < 2; ms++)
        abase[ms] = sbase + (wm + ms * 16 + (mat & 1) * 8 + mi) * A_ROW_B + (mat >> 1) * 16;
    uint32_t bloff[4];
    #pragma unroll
    for (int p = 0; p < 4; p++)
        bloff[p] = (wn + p * 16 + (mat >> 1) * 8 + mi) * B_ROW_B + (mat & 1) * 16;

    float acc[2][8][4];
    float rmax4[4] = {-3.0e38f, -3.0e38f, -3.0e38f, -3.0e38f};
    int cbuf = 0, wbuf = 2;
    int fnt = 0, fkc = 2;
    int j = 0;

    for (int nt = 0; nt < 8; nt++) {
        #pragma unroll
        for (int ms = 0; ms < 2; ms++)
            #pragma unroll
            for (int ns = 0; ns < 8; ns++)
                #pragma unroll
                for (int v = 0; v < 4; v++) acc[ms][ns][v] = 0.f;

        for (int kc = 0; kc < 10; kc++, j++) {
            if (j < 78) {
                loadB(fnt << 7, fkc, wbuf);
                if (++wbuf == N_STAGE) wbuf = 0;
                if (++fkc == 10) { fkc = 0; fnt++; }
                CP_WAIT(2);
            } else if (j == 78) { CP_WAIT(1); }
            else                { CP_WAIT(0); }
            __syncthreads();

            const uint32_t bb = sbase + B_OFF + cbuf * B_BUF_B;
            const uint32_t akb = (uint32_t)kc * 128;
            #pragma unroll
            for (int ks = 0; ks < 4; ks++) {
                uint32_t a0[4], a1[4], br[4];
                ldsm_x4(a0, abase[0] + akb + ks * 32);
                ldsm_x4(a1, abase[1] + akb + ks * 32);
                #pragma unroll
                for (int p = 0; p < 4; p++) {
                    ldsm_x4(br, bb + bloff[p] + ks * 32);
                    mma16816(acc[0][2 * p + 0], a0, &br[0]);
                    mma16816(acc[0][2 * p + 1], a0, &br[2]);
                    mma16816(acc[1][2 * p + 0], a1, &br[0]);
                    mma16816(acc[1][2 * p + 1], a1, &br[2]);
                }
            }
            if (++cbuf == N_STAGE) cbuf = 0;
            __syncthreads();
        }
        #pragma unroll
        for (int ms = 0; ms < 2; ms++)
            #pragma unroll
            for (int ns = 0; ns < 8; ns++) {
                rmax4[ms * 2 + 0] = fmaxf(rmax4[ms * 2 + 0], fmaxf(acc[ms][ns][0], acc[ms][ns][1]));
                rmax4[ms * 2 + 1] = fmaxf(rmax4[ms * 2 + 1], fmaxf(acc[ms][ns][2], acc[ms][ns][3]));
            }
    }

    // reduce: lanes t -> apply 1/||q_row|| -> warpN pairs -> sum 128 rowmaxes
    float* rs = reinterpret_cast<float*>(sm + RS_OFF);
    #pragma unroll
    for (int m4 = 0; m4 < 4; m4++) {
        float v = rmax4[m4];
        v = fmaxf(v, __shfl_xor_sync(0xffffffffu, v, 1));
        v = fmaxf(v, __shfl_xor_sync(0xffffffffu, v, 2));
        rmax4[m4] = v;
    }
    if (t == 0) {
        rs[wid * 32 + g]      = rmax4[0] * invn[wm + g];
        rs[wid * 32 + 8 + g]  = rmax4[1] * invn[wm + 8 + g];
        rs[wid * 32 + 16 + g] = rmax4[2] * invn[wm + 16 + g];
        rs[wid * 32 + 24 + g] = rmax4[3] * invn[wm + 24 + g];
    }
    __syncthreads();
    if (tid < 128) {
        int wmi = tid >> 5, r = tid & 31;
        float v = fmaxf(rs[(2 * wmi) * 32 + r], rs[(2 * wmi + 1) * 32 + r]);
        #pragma unroll
        for (int o = 16; o; o >>= 1) v += __shfl_xor_sync(0xffffffffu, v, o);
        if ((tid & 31) == 0) rs[256 + (tid >> 5)] = v;
    }
    __syncthreads();
    if (tid == 0) g_part[bid] = rs[256] + rs[257] + rs[258] + rs[259];
}

// ---------------- P4: deterministic reduce ----------------------------------
__global__ void finalize_kernel(float* __restrict__ out) {
    int q = threadIdx.x;
    float s = 0.f;
    #pragma unroll
    for (int mt = 0; mt < 8; mt++) s += g_part[q * 8 + mt];
    out[q] = s * (1.0f / 1024.0f);
}

extern "C" void kernel_launch(void* const* d_in, const int* in_sizes, int n_in,
                              void* d_out, int out_size) {
    const float* qf = (const float*)d_in[0];
    const float* sf = (const float*)d_in[1];
    float* out = (float*)d_out;
    cudaFuncSetAttribute(sim_kernel, cudaFuncAttributeMaxDynamicSharedMemorySize, MAIN_SMEM);
    prep_support<<<128, 256>>>(sf);
    sim_kernel<<<1024, 256, MAIN_SMEM>>>(qf);
    finalize_kernel<<<1, 128>>>(out);
}

// round 17
// speedup vs baseline: 1.8026x; 1.0107x over previous
#include <cuda_runtime.h>
#include <cuda_fp16.h>
#include <cstdint>
#include <cstddef>

#define NQ 128
#define CDIM 640
#define NP 1024

// A: 128 rows x 648 f16 (row 1296 B; stride%128==16 -> LDSM conflict-free)
#define A_ROW_B 1296
#define A_BYTES (128 * A_ROW_B)               /* 165888 */
#define B_OFF   A_BYTES
#define B_ROW_B 144
#define B_BUF_B (128 * B_ROW_B)               /* 18432 */
#define N_STAGE 3
#define NORM_OFF (B_OFF + N_STAGE * B_BUF_B)  /* 221184: inv-norms[128] f32 */
#define RS_OFF   (NORM_OFF + 512)             /* 221696 */
#define MAIN_SMEM (RS_OFF + (8 * 32 + 8) * 4) /* 222752 */
#define STG_PAD 130

__device__ __align__(16) __half g_s[(size_t)NP * CDIM];   // [n][c] normalized proto
__device__ float g_part[NQ * 8];

__device__ __forceinline__ uint32_t smem_u32(const void* p) {
    uint32_t a;
    asm("{ .reg .u64 t; cvta.to.shared.u64 t, %1; cvt.u32.u64 %0, t; }" : "=r"(a) : "l"(p));
    return a;
}
#define CP_ASYNC16(dst, src) \
    asm volatile("cp.async.cg.shared.global [%0], [%1], 16;" :: "r"(dst), "l"(src) : "memory")
#define CP_COMMIT() asm volatile("cp.async.commit_group;" ::: "memory")
#define CP_WAIT(n)  asm volatile("cp.async.wait_group %0;" :: "n"(n) : "memory")

__device__ __forceinline__ void ldsm_x4(uint32_t* r, uint32_t a) {
    asm volatile("ldmatrix.sync.aligned.m8n8.x4.shared.b16 {%0,%1,%2,%3}, [%4];"
        : "=r"(r[0]), "=r"(r[1]), "=r"(r[2]), "=r"(r[3]) : "r"(a));
}
__device__ __forceinline__ void mma16816(float* c, const uint32_t* a, const uint32_t* b) {
    asm volatile(
        "mma.sync.aligned.m16n8k16.row.col.f32.f16.f16.f32 "
        "{%0,%1,%2,%3}, {%4,%5,%6,%7}, {%8,%9}, {%0,%1,%2,%3};"
        : "+f"(c[0]), "+f"(c[1]), "+f"(c[2]), "+f"(c[3])
        : "r"(a[0]), "r"(a[1]), "r"(a[2]), "r"(a[3]), "r"(b[0]), "r"(b[1]));
}

// ---------------- P1: support prototype + L2 norm -> g_s f16 [n][c] --------
// grid 256 x 4 rows: 2x CTAs vs round 16, input read once (smem proto cache).
__global__ void __launch_bounds__(256, 1) prep_support(const float* __restrict__ sup) {
    __shared__ float proto[4 * 648];
    __shared__ float red[256];
    __shared__ float inv[4];
    const int tid = threadIdx.x;
    const int r = tid >> 2, ml = tid & 3;          // 64 channel lanes x 4 rows
    const int m0 = blockIdx.x * 4;
    const float* base = sup + m0 + ml;
    float ssq = 0.f;
    for (int c = r; c < CDIM; c += 64) {
        float s = 0.f;
        #pragma unroll
        for (int sh = 0; sh < 5; sh++) s += base[((size_t)sh * CDIM + c) * NP];
        float p = s * 0.2f;
        proto[ml * 648 + c] = p;
        ssq += p * p;
    }
    red[tid] = ssq;
    __syncthreads();
    if (tid < 4) {
        float s = 0.f;
        #pragma unroll
        for (int rr = 0; rr < 64; rr++) s += red[tid + 4 * rr];
        inv[tid] = 1.f / fmaxf(sqrtf(s), 1e-12f);
    }
    __syncthreads();
    const float iv = inv[ml];
    __half* dst = g_s + (size_t)(m0 + ml) * CDIM;
    for (int c = r; c < CDIM; c += 64)
        dst[c] = __float2half_rn(proto[ml * 648 + c] * iv);
}

// ---------------- launch-slot shims: land ncu's capture on sim_kernel -------
__global__ void noop_kernel() {}

// ---------------- P2(main): fused A-prep + HMMA GEMM + rowmax ---------------
// (byte-identical mainloop to round 16 — kept frozen for a clean profile)
__global__ void __launch_bounds__(256, 1) sim_kernel(const float* __restrict__ qf) {
    extern __shared__ unsigned char sm[];
    const uint32_t sbase = smem_u32(sm);
    const int tid = threadIdx.x, wid = tid >> 5, lid = tid & 31;
    const int g = lid >> 2, t = lid & 3;
    const int mat = lid >> 3, mi = lid & 7;
    const int wm = (wid >> 1) * 32, wn = (wid & 1) * 64;
    const int bid = blockIdx.x, q = bid >> 3, mt = bid & 7;

    // ======== A-prep staging: 10 chunks of 64 c x 128 n ========
    float* stage = reinterpret_cast<float*>(sm + B_OFF);   // [64][130]
    float* invn  = reinterpret_cast<float*>(sm + NORM_OFF);
    const int c_l = tid >> 3, w = tid & 7;
    const int pn = tid >> 1, pcg = tid & 1;
    const float4* q4 = reinterpret_cast<const float4*>(qf)
                     + ((size_t)q * CDIM) * 256 + mt * 32;
    __half* Ah = reinterpret_cast<__half*>(sm);
    float ss = 0.f;

    for (int i = 0; i < 10; i++) {
        {
            const float4* qc = q4 + (size_t)(i * 64 + c_l) * 256;
            float4 rr[8];
            #pragma unroll
            for (int k = 0; k < 4; k++) rr[k] = qc[w + 8 * k];
            #pragma unroll
            for (int k = 0; k < 4; k++) rr[4 + k] = qc[(size_t)32 * 256 + w + 8 * k];
            #pragma unroll
            for (int k = 0; k < 4; k++) {
                float* s0 = stage + c_l * STG_PAD + (w + 8 * k) * 4;
                s0[0] = rr[k].x; s0[1] = rr[k].y; s0[2] = rr[k].z; s0[3] = rr[k].w;
                float* s1 = stage + (c_l + 32) * STG_PAD + (w + 8 * k) * 4;
                s1[0] = rr[4+k].x; s1[1] = rr[4+k].y; s1[2] = rr[4+k].z; s1[3] = rr[4+k].w;
            }
        }
        __syncthreads();
        {
            const int c0 = i * 64;
            __half hprev = __float2half_rn(0.f);
            #pragma unroll
            for (int ii = 0; ii < 32; ii++) {
                int cl = ((ii >> 3) << 4) + pcg * 8 + (ii & 7);
                float v = stage[cl * STG_PAD + pn];
                ss += v * v;
                __half h = __float2half_rn(v);
                if (ii & 1) {
                    __half2 h2 = __halves2half2(hprev, h);
                    *reinterpret_cast<__half2*>(
                        reinterpret_cast<char*>(Ah) + pn * A_ROW_B + (c0 + cl - 1) * 2) = h2;
                }
                hprev = h;
            }
        }
        __syncthreads();
    }
    {
        float s2 = ss + __shfl_xor_sync(0xffffffffu, ss, 1);
        if (pcg == 0) invn[pn] = 1.f / fmaxf(sqrtf(s2), 1e-12f);
    }
    __syncthreads();

    // ======== mainloop (f16 operands) ========
    const int r8 = tid >> 3, c8 = tid & 7;
    auto loadB = [&](int n0, int kc, int buf) {
        uint32_t dstb = sbase + B_OFF + buf * B_BUF_B;
        const __half* s0 = g_s + (size_t)n0 * CDIM + kc * 64 + c8 * 8;
        #pragma unroll
        for (int it = 0; it < 4; it++) {
            int r = r8 + it * 32;
            CP_ASYNC16(dstb + r * B_ROW_B + c8 * 16, s0 + (size_t)r * CDIM);
        }
        CP_COMMIT();
    };
    loadB(0, 0, 0);
    loadB(0, 1, 1);

    uint32_t abase[2];
    #pragma unroll
    for (int ms = 0; ms < 2; ms++)
        abase[ms] = sbase + (wm + ms * 16 + (mat & 1) * 8 + mi) * A_ROW_B + (mat >> 1) * 16;
    uint32_t bloff[4];
    #pragma unroll
    for (int p = 0; p < 4; p++)
        bloff[p] = (wn + p * 16 + (mat >> 1) * 8 + mi) * B_ROW_B + (mat & 1) * 16;

    float acc[2][8][4];
    float rmax4[4] = {-3.0e38f, -3.0e38f, -3.0e38f, -3.0e38f};
    int cbuf = 0, wbuf = 2;
    int fnt = 0, fkc = 2;
    int j = 0;

    for (int nt = 0; nt < 8; nt++) {
        #pragma unroll
        for (int ms = 0; ms < 2; ms++)
            #pragma unroll
            for (int ns = 0; ns < 8; ns++)
                #pragma unroll
                for (int v = 0; v < 4; v++) acc[ms][ns][v] = 0.f;

        for (int kc = 0; kc < 10; kc++, j++) {
            if (j < 78) {
                loadB(fnt << 7, fkc, wbuf);
                if (++wbuf == N_STAGE) wbuf = 0;
                if (++fkc == 10) { fkc = 0; fnt++; }
                CP_WAIT(2);
            } else if (j == 78) { CP_WAIT(1); }
            else                { CP_WAIT(0); }
            __syncthreads();

            const uint32_t bb = sbase + B_OFF + cbuf * B_BUF_B;
            const uint32_t akb = (uint32_t)kc * 128;
            #pragma unroll
            for (int ks = 0; ks < 4; ks++) {
                uint32_t a0[4], a1[4], br[4];
                ldsm_x4(a0, abase[0] + akb + ks * 32);
                ldsm_x4(a1, abase[1] + akb + ks * 32);
                #pragma unroll
                for (int p = 0; p < 4; p++) {
                    ldsm_x4(br, bb + bloff[p] + ks * 32);
                    mma16816(acc[0][2 * p + 0], a0, &br[0]);
                    mma16816(acc[0][2 * p + 1], a0, &br[2]);
                    mma16816(acc[1][2 * p + 0], a1, &br[0]);
                    mma16816(acc[1][2 * p + 1], a1, &br[2]);
                }
            }
            if (++cbuf == N_STAGE) cbuf = 0;
            __syncthreads();
        }
        #pragma unroll
        for (int ms = 0; ms < 2; ms++)
            #pragma unroll
            for (int ns = 0; ns < 8; ns++) {
                rmax4[ms * 2 + 0] = fmaxf(rmax4[ms * 2 + 0], fmaxf(acc[ms][ns][0], acc[ms][ns][1]));
                rmax4[ms * 2 + 1] = fmaxf(rmax4[ms * 2 + 1], fmaxf(acc[ms][ns][2], acc[ms][ns][3]));
            }
    }

    // reduce: lanes t -> apply 1/||q_row|| -> warpN pairs -> sum 128 rowmaxes
    float* rs = reinterpret_cast<float*>(sm + RS_OFF);
    #pragma unroll
    for (int m4 = 0; m4 < 4; m4++) {
        float v = rmax4[m4];
        v = fmaxf(v, __shfl_xor_sync(0xffffffffu, v, 1));
        v = fmaxf(v, __shfl_xor_sync(0xffffffffu, v, 2));
        rmax4[m4] = v;
    }
    if (t == 0) {
        rs[wid * 32 + g]      = rmax4[0] * invn[wm + g];
        rs[wid * 32 + 8 + g]  = rmax4[1] * invn[wm + 8 + g];
        rs[wid * 32 + 16 + g] = rmax4[2] * invn[wm + 16 + g];
        rs[wid * 32 + 24 + g] = rmax4[3] * invn[wm + 24 + g];
    }
    __syncthreads();
    if (tid < 128) {
        int wmi = tid >> 5, r = tid & 31;
        float v = fmaxf(rs[(2 * wmi) * 32 + r], rs[(2 * wmi + 1) * 32 + r]);
        #pragma unroll
        for (int o = 16; o; o >>= 1) v += __shfl_xor_sync(0xffffffffu, v, o);
        if ((tid & 31) == 0) rs[256 + (tid >> 5)] = v;
    }
    __syncthreads();
    if (tid == 0) g_part[bid] = rs[256] + rs[257] + rs[258] + rs[259];
}

// ---------------- P4: deterministic reduce ----------------------------------
__global__ void finalize_kernel(float* __restrict__ out) {
    int q = threadIdx.x;
    float s = 0.f;
    #pragma unroll
    for (int mt = 0; mt < 8; mt++) s += g_part[q * 8 + mt];
    out[q] = s * (1.0f / 1024.0f);
}

extern "C" void kernel_launch(void* const* d_in, const int* in_sizes, int n_in,
                              void* d_out, int out_size) {
    const float* qf = (const float*)d_in[0];
    const float* sf = (const float*)d_in[1];
    float* out = (float*)d_out;
    cudaFuncSetAttribute(sim_kernel, cudaFuncAttributeMaxDynamicSharedMemorySize, MAIN_SMEM);
    prep_support<<<256, 256>>>(sf);     // launch 1
    noop_kernel<<<1, 32>>>();           // launch 2 (profiler slot shim)
    noop_kernel<<<1, 32>>>();           // launch 3 (profiler slot shim)
    sim_kernel<<<1024, 256, MAIN_SMEM>>>(qf);   // launch 4 <- ncu capture slot
    finalize_kernel<<<1, 128>>>(out);   // launch 5
}